// round 15
// baseline (speedup 1.0000x reference)
#include <cuda_runtime.h>

#define NN 200000
#define EE 6400000
#define GG 2048
#define HH 32
#define CAP 128          // fixed bucket capacity; P(deg>128) ~ e^-100 for this input

// ---------------- scratch -----------------------------------------------------
__device__ int   g_cnt[NN];                      // per-node degree counter (zeroed)
__device__ float g_sx[NN];                       // per-node sum of x[src] (zeroed)
__device__ __align__(16) float2 g_mx[NN];        // (m, x)
__device__ int   g_csrf[NN * CAP];               // fixed-stride CSR buckets
__device__ __align__(16) float g_h2[NN * HH];
__device__ float g_s5[5];
__device__ float g_stats[2 * HH];
__device__ __align__(16) float g_A[HH], g_B[HH], g_C[HH];
__device__ float g_scale2[HH], g_shift2[HH];
__device__ int   g_cnt1, g_cnt2;

// ---------------- kernels -----------------------------------------------------

// single edge pass: rank via int atomic, bucket write, float reduction of x[src]
__global__ void k_edge1(const int* __restrict__ ei, const float* __restrict__ x) {
    int e = blockIdx.x * blockDim.x + threadIdx.x;   // covers EE exactly
    int s = __ldg(&ei[e]);
    int d = __ldg(&ei[EE + e]);
    float xv = __ldg(&x[s]);
    int r = atomicAdd(&g_cnt[d], 1);
    g_csrf[(d << 7) + r] = s;
    asm volatile("red.global.add.f32 [%0], %1;"
                 :: "l"(&g_sx[d]), "f"(xv) : "memory");
}

// per-node (m,x) + 5 moments; last block computes A,B,C
__global__ void k_mx(const float* __restrict__ x, const float* __restrict__ W1l,
                     const float* __restrict__ b1l, const float* __restrict__ W1r,
                     const float* __restrict__ g1, const float* __restrict__ be1) {
    int i = blockIdx.x * blockDim.x + threadIdx.x;
    float m = 0.f, xv = 0.f;
    if (i < NN) {
        float dc = (float)g_cnt[i];
        m = g_sx[i] / fmaxf(dc, 1.f);
        xv = __ldg(&x[i]);
        g_mx[i] = make_float2(m, xv);
    }
    float v0 = m, v1 = xv, v2 = m * m, v3 = xv * xv, v4 = m * xv;
#pragma unroll
    for (int o = 16; o; o >>= 1) {
        v0 += __shfl_xor_sync(0xffffffffu, v0, o);
        v1 += __shfl_xor_sync(0xffffffffu, v1, o);
        v2 += __shfl_xor_sync(0xffffffffu, v2, o);
        v3 += __shfl_xor_sync(0xffffffffu, v3, o);
        v4 += __shfl_xor_sync(0xffffffffu, v4, o);
    }
    if ((threadIdx.x & 31) == 0) {
        atomicAdd(&g_s5[0], v0); atomicAdd(&g_s5[1], v1);
        atomicAdd(&g_s5[2], v2); atomicAdd(&g_s5[3], v3);
        atomicAdd(&g_s5[4], v4);
    }
    __syncthreads();
    if (threadIdx.x == 0) {
        __threadfence();
        if (atomicAdd(&g_cnt1, 1) == gridDim.x - 1) {
            float s0 = atomicAdd(&g_s5[0], 0.f), s1 = atomicAdd(&g_s5[1], 0.f);
            float s2 = atomicAdd(&g_s5[2], 0.f), s3 = atomicAdd(&g_s5[3], 0.f);
            float s4 = atomicAdd(&g_s5[4], 0.f);
            float invN = 1.f / (float)NN;
            float Mm = s0 * invN, Mx = s1 * invN;
            float Vm = s2 * invN - Mm * Mm;
            float Vx = s3 * invN - Mx * Mx;
            float Cmx = s4 * invN - Mm * Mx;
            for (int f = 0; f < HH; f++) {
                float wl = __ldg(&W1l[f]), wr = __ldg(&W1r[f]), b = __ldg(&b1l[f]);
                float mean = wl * Mm + wr * Mx + b;
                float var = wl * wl * Vm + wr * wr * Vx + 2.f * wl * wr * Cmx;
                float sc = __ldg(&g1[f]) * rsqrtf(var + 1e-5f);
                g_A[f] = sc * wl;
                g_B[f] = sc * wr;
                g_C[f] = sc * b + __ldg(&be1[f]) - sc * mean;
            }
        }
    }
}

// fused layer-2: bucket gather of (m,x), smem-staged float2 broadcasts,
// packed-weight matmul, BN2 stats; last block finalizes BN2 scale/shift.
__global__ void k_l2g(const float* __restrict__ W2l, const float* __restrict__ b2l,
                      const float* __restrict__ W2r, const float* __restrict__ g2,
                      const float* __restrict__ be2) {
    __shared__ float2 sW[HH][HH];       // sW[j][i] = (W2l[i][j], W2r[i][j])
    __shared__ float sb[HH];
    __shared__ float2 stage[8][HH];     // per-warp staging buffer

    for (int t = threadIdx.x; t < HH * HH; t += blockDim.x) {
        int i = t >> 5, j = t & 31;
        sW[j][i] = make_float2(__ldg(&W2l[i * HH + j]), __ldg(&W2r[i * HH + j]));
    }
    if (threadIdx.x < HH) sb[threadIdx.x] = __ldg(&b2l[threadIdx.x]);
    __syncthreads();

    int lane = threadIdx.x & 31;
    int wid  = threadIdx.x >> 5;
    int warp = (blockIdx.x * blockDim.x + threadIdx.x) >> 5;
    int nwarps = (gridDim.x * blockDim.x) >> 5;
    float A = g_A[lane], B = g_B[lane], C = g_C[lane];
    float s = 0.f, s2 = 0.f;
    float2* st = stage[wid];

    for (int n = warp; n < NN; n += nwarps) {
        int off = n << 7;
        int deg = g_cnt[n];
        int full = deg & ~31;
        float acc = 0.f;
        for (int base = 0; base < full; base += 32) {
            float2 mxe = __ldg(&g_mx[__ldg(&g_csrf[off + base + lane])]);
            __syncwarp();
            st[lane] = mxe;
            __syncwarp();
            float a0 = 0.f, a1 = 0.f, a2 = 0.f, a3 = 0.f;
#pragma unroll
            for (int j = 0; j < 32; j += 4) {
                float2 u0 = st[j];
                float2 u1 = st[j + 1];
                float2 u2 = st[j + 2];
                float2 u3 = st[j + 3];
                a0 += fmaxf(fmaf(A, u0.x, fmaf(B, u0.y, C)), 0.f);
                a1 += fmaxf(fmaf(A, u1.x, fmaf(B, u1.y, C)), 0.f);
                a2 += fmaxf(fmaf(A, u2.x, fmaf(B, u2.y, C)), 0.f);
                a3 += fmaxf(fmaf(A, u3.x, fmaf(B, u3.y, C)), 0.f);
            }
            acc += (a0 + a1) + (a2 + a3);
        }
        int rem = deg - full;
        if (rem) {
            float2 mxe = make_float2(0.f, 0.f);
            if (lane < rem) mxe = __ldg(&g_mx[__ldg(&g_csrf[off + full + lane])]);
            __syncwarp();
            st[lane] = mxe;
            __syncwarp();
            for (int j = 0; j < rem; j++) {
                float2 u = st[j];
                acc += fmaxf(fmaf(A, u.x, fmaf(B, u.y, C)), 0.f);
            }
        }
        float av = acc / fmaxf((float)deg, 1.f);
        float2 mxn = g_mx[n];
        float hr = fmaxf(fmaf(A, mxn.x, fmaf(B, mxn.y, C)), 0.f);
        __syncwarp();
        st[lane] = make_float2(av, hr);
        __syncwarp();
        float o0 = sb[lane], o1 = 0.f, o2 = 0.f, o3 = 0.f;
#pragma unroll
        for (int j = 0; j < 32; j += 4) {
            float2 u0 = st[j];     float2 w0 = sW[j][lane];
            float2 u1 = st[j + 1]; float2 w1 = sW[j + 1][lane];
            float2 u2 = st[j + 2]; float2 w2 = sW[j + 2][lane];
            float2 u3 = st[j + 3]; float2 w3 = sW[j + 3][lane];
            o0 = fmaf(u0.x, w0.x, fmaf(u0.y, w0.y, o0));
            o1 = fmaf(u1.x, w1.x, fmaf(u1.y, w1.y, o1));
            o2 = fmaf(u2.x, w2.x, fmaf(u2.y, w2.y, o2));
            o3 = fmaf(u3.x, w3.x, fmaf(u3.y, w3.y, o3));
        }
        float outv = (o0 + o1) + (o2 + o3);
        g_h2[n * HH + lane] = outv;
        s += outv; s2 += outv * outv;
    }
    atomicAdd(&g_stats[lane], s);
    atomicAdd(&g_stats[HH + lane], s2);

    __syncthreads();
    if (threadIdx.x == 0) {
        __threadfence();
        if (atomicAdd(&g_cnt2, 1) == gridDim.x - 1) {
            float invN = 1.f / (float)NN;
            for (int f = 0; f < HH; f++) {
                float sum = atomicAdd(&g_stats[f], 0.f);
                float sq  = atomicAdd(&g_stats[HH + f], 0.f);
                float mean = sum * invN;
                float var = sq * invN - mean * mean;
                float sc = __ldg(&g2[f]) * rsqrtf(var + 1e-5f);
                g_scale2[f] = sc;
                g_shift2[f] = __ldg(&be2[f]) - mean * sc;
            }
        }
    }
}

__device__ __forceinline__ int lbound(const int* __restrict__ a, int n, int v) {
    int lo = 0, hi = n;
    while (lo < hi) {
        int mid = (lo + hi) >> 1;
        if (__ldg(&a[mid]) < v) lo = mid + 1; else hi = mid;
    }
    return lo;
}

// pooling: block per graph; single-pass online softmax.
__global__ void k_pool(const int* __restrict__ batch,
                       const float* __restrict__ gw, const float* __restrict__ gb,
                       const float* __restrict__ lw, const float* __restrict__ lb,
                       float* __restrict__ out) {
    int g = blockIdx.x;
    int lane = threadIdx.x & 31;
    int wid = threadIdx.x >> 5;                      // 4 warps
    int lo = lbound(batch, NN, g);
    int hi = lbound(batch, NN, g + 1);
    float lbv = __ldg(&lb[0]);
    if (lo >= hi) {
        if (threadIdx.x == 0) out[g] = 1.f / (1.f + expf(-lbv));
        return;
    }
    float w = __ldg(&gw[lane]);
    float gbv = __ldg(&gb[0]);
    float sc2 = g_scale2[lane], sh2 = g_shift2[lane];

    __shared__ float smax[4], sden[4], snum[4][HH];

    float mxs = -3.4e38f, den = 0.f, num = 0.f;
    for (int n = lo + wid; n < hi; n += 4) {
        float v = fmaxf(g_h2[n * HH + lane] * sc2 + sh2, 0.f);
        float sc = v * w;
#pragma unroll
        for (int o = 16; o; o >>= 1) sc += __shfl_xor_sync(0xffffffffu, sc, o);
        sc += gbv;
        if (sc > mxs) {
            float r = expf(mxs - sc);
            den *= r; num *= r;
            mxs = sc;
        }
        float ex = expf(sc - mxs);
        den += ex;
        num += ex * v;
    }
    if (lane == 0) smax[wid] = mxs;
    __syncthreads();
    float bmax = fmaxf(fmaxf(smax[0], smax[1]), fmaxf(smax[2], smax[3]));
    float r = expf(mxs - bmax);
    snum[wid][lane] = num * r;
    if (lane == 0) sden[wid] = den * r;
    __syncthreads();
    if (wid == 0) {
        float nm = snum[0][lane] + snum[1][lane] + snum[2][lane] + snum[3][lane];
        float dn = sden[0] + sden[1] + sden[2] + sden[3];
        float val = nm / dn * __ldg(&lw[lane]);
#pragma unroll
        for (int o = 16; o; o >>= 1) val += __shfl_xor_sync(0xffffffffu, val, o);
        if (lane == 0) out[g] = 1.f / (1.f + expf(-(val + lbv)));
    }
}

// cleanup: restore the zero-state invariant for the next graph replay
__global__ void k_clean() {
    int i = blockIdx.x * blockDim.x + threadIdx.x;
    if (i < NN) { g_cnt[i] = 0; g_sx[i] = 0.f; }
    if (i < 5) g_s5[i] = 0.f;
    if (i < 2 * HH) g_stats[i] = 0.f;
    if (i == 0) { g_cnt1 = 0; g_cnt2 = 0; }
}

// ---------------- launch -------------------------------------------------------

extern "C" void kernel_launch(void* const* d_in, const int* in_sizes, int n_in,
                              void* d_out, int out_size) {
    const float* x     = (const float*)d_in[0];
    const int*   ei    = (const int*)d_in[1];
    const int*   batch = (const int*)d_in[2];
    const float* W1l   = (const float*)d_in[3];
    const float* b1l   = (const float*)d_in[4];
    const float* W1r   = (const float*)d_in[5];
    const float* W2l   = (const float*)d_in[6];
    const float* b2l   = (const float*)d_in[7];
    const float* W2r   = (const float*)d_in[8];
    const float* g1    = (const float*)d_in[9];
    const float* be1   = (const float*)d_in[10];
    const float* g2    = (const float*)d_in[11];
    const float* be2   = (const float*)d_in[12];
    const float* gate_w= (const float*)d_in[13];
    const float* gate_b= (const float*)d_in[14];
    const float* lin_w = (const float*)d_in[15];
    const float* lin_b = (const float*)d_in[16];
    float* out = (float*)d_out;

    const int T = 256;
    const int blocksE = EE / T;                  // 25000
    const int blocksN = (NN + T - 1) / T;        // 782
    const int blocksW = 2048;

    k_edge1<<<blocksE, T>>>(ei, x);                               // 1
    k_mx<<<blocksN, T>>>(x, W1l, b1l, W1r, g1, be1);              // 2
    k_l2g<<<blocksW, T>>>(W2l, b2l, W2r, g2, be2);                // 3
    k_pool<<<GG, 128>>>(batch, gate_w, gate_b, lin_w, lin_b, out);// 4  <- profiled slot
    k_clean<<<blocksN, T>>>();                                    // 5
}

// round 16
// speedup vs baseline: 1.0094x; 1.0094x over previous
#include <cuda_runtime.h>

#define NN 200000
#define EE 6400000
#define GG 2048
#define HH 32
#define NB2 196   // ceil(NN/1024)

// ---------------- scratch -----------------------------------------------------
__device__ __align__(16) float2 g_ad[NN];        // (sum_x, deg); zeroed by k_clean/static init
__device__ __align__(16) float2 g_mx[NN];        // (m, x)
__device__ int   g_off[NN];
__device__ int   g_cursor[NN];
__device__ int   g_bsum[NB2];
__device__ int   g_csr[EE];
__device__ __align__(16) float g_h2[NN * HH];
__device__ float g_s5[5];
__device__ float g_stats[2 * HH];
__device__ __align__(16) float g_A[HH], g_B[HH], g_C[HH];
__device__ float g_scale2[HH], g_shift2[HH];
__device__ int   g_cnt0, g_cnt1, g_cnt2;

// ---------------- kernels -----------------------------------------------------

__global__ void k_edge1(const int* __restrict__ ei, const float* __restrict__ x) {
    int e = blockIdx.x * blockDim.x + threadIdx.x;   // covers EE exactly
    int s = __ldg(&ei[e]);
    int d = __ldg(&ei[EE + e]);
    float xv = __ldg(&x[s]);
    float* p = (float*)&g_ad[d];
    asm volatile("red.global.add.v2.f32 [%0], {%1,%2};"
                 :: "l"(p), "f"(xv), "f"(1.0f) : "memory");
}

// fused scan: per-block tile scan + device-wide spin barrier + base recompute,
// then offsets/cursor/(m,x)/moments; last block computes A,B,C.
__global__ void k_scan(const float* __restrict__ x, const float* __restrict__ W1l,
                       const float* __restrict__ b1l, const float* __restrict__ W1r,
                       const float* __restrict__ g1, const float* __restrict__ be1) {
    __shared__ int sm[256];
    __shared__ int sw[8];
    int b = blockIdx.x, t = threadIdx.x;
    int lane = t & 31, wid = t >> 5;
    int n0 = b * 1024 + t * 4;

    int s = 0;
#pragma unroll
    for (int k = 0; k < 4; k++) { int n = n0 + k; if (n < NN) s += (int)g_ad[n].y; }
    sm[t] = s; __syncthreads();
    for (int o = 1; o < 256; o <<= 1) {
        int u = (t >= o) ? sm[t - o] : 0;
        __syncthreads(); sm[t] += u; __syncthreads();
    }
    int ex = sm[t] - s;
    if (t == 255) g_bsum[b] = sm[255];

    __syncthreads();
    if (t == 0) {
        __threadfence();
        atomicAdd(&g_cnt0, 1);
        while (atomicAdd(&g_cnt0, 0) < (int)gridDim.x) { }
    }
    __syncthreads();
    __threadfence();

    int v = (t < b) ? g_bsum[t] : 0;
    int r = v;
#pragma unroll
    for (int o = 16; o; o >>= 1) r += __shfl_xor_sync(0xffffffffu, r, o);
    if (lane == 0) sw[wid] = r;
    __syncthreads();
    int base = sw[0] + sw[1] + sw[2] + sw[3] + sw[4] + sw[5] + sw[6] + sw[7] + ex;

    float m0 = 0.f, m1 = 0.f, m2 = 0.f, m3 = 0.f, m4 = 0.f;
#pragma unroll
    for (int k = 0; k < 4; k++) {
        int n = n0 + k;
        if (n < NN) {
            float2 ad = g_ad[n];
            g_off[n] = base; g_cursor[n] = base;
            base += (int)ad.y;
            float m = ad.x / fmaxf(ad.y, 1.f);
            float xv = __ldg(&x[n]);
            g_mx[n] = make_float2(m, xv);
            m0 += m; m1 += xv; m2 += m * m; m3 += xv * xv; m4 += m * xv;
        }
    }
#pragma unroll
    for (int o = 16; o; o >>= 1) {
        m0 += __shfl_xor_sync(0xffffffffu, m0, o);
        m1 += __shfl_xor_sync(0xffffffffu, m1, o);
        m2 += __shfl_xor_sync(0xffffffffu, m2, o);
        m3 += __shfl_xor_sync(0xffffffffu, m3, o);
        m4 += __shfl_xor_sync(0xffffffffu, m4, o);
    }
    if (lane == 0) {
        atomicAdd(&g_s5[0], m0); atomicAdd(&g_s5[1], m1);
        atomicAdd(&g_s5[2], m2); atomicAdd(&g_s5[3], m3);
        atomicAdd(&g_s5[4], m4);
    }
    __syncthreads();
    if (t == 0) {
        __threadfence();
        if (atomicAdd(&g_cnt1, 1) == gridDim.x - 1) {
            float s0 = atomicAdd(&g_s5[0], 0.f), s1 = atomicAdd(&g_s5[1], 0.f);
            float s2 = atomicAdd(&g_s5[2], 0.f), s3 = atomicAdd(&g_s5[3], 0.f);
            float s4 = atomicAdd(&g_s5[4], 0.f);
            float invN = 1.f / (float)NN;
            float Mm = s0 * invN, Mx = s1 * invN;
            float Vm = s2 * invN - Mm * Mm;
            float Vx = s3 * invN - Mx * Mx;
            float Cmx = s4 * invN - Mm * Mx;
            for (int f = 0; f < HH; f++) {
                float wlv = __ldg(&W1l[f]), wrv = __ldg(&W1r[f]), bv = __ldg(&b1l[f]);
                float mean = wlv * Mm + wrv * Mx + bv;
                float var = wlv * wlv * Vm + wrv * wrv * Vx + 2.f * wlv * wrv * Cmx;
                float sc = __ldg(&g1[f]) * rsqrtf(var + 1e-5f);
                g_A[f] = sc * wlv;
                g_B[f] = sc * wrv;
                g_C[f] = sc * bv + __ldg(&be1[f]) - sc * mean;
            }
        }
    }
}

// index scatter with 4-way ILP
__global__ void k_scatter(const int* __restrict__ ei) {
    const int total = (EE / 4);
    int t = blockIdx.x * blockDim.x + threadIdx.x;   // grid covers EE/4 exactly
    int e0 = t, e1 = t + total, e2 = t + 2 * total, e3 = t + 3 * total;
    int s0 = __ldg(&ei[e0]), s1 = __ldg(&ei[e1]);
    int s2 = __ldg(&ei[e2]), s3 = __ldg(&ei[e3]);
    int d0 = __ldg(&ei[EE + e0]), d1 = __ldg(&ei[EE + e1]);
    int d2 = __ldg(&ei[EE + e2]), d3 = __ldg(&ei[EE + e3]);
    int p0 = atomicAdd(&g_cursor[d0], 1);
    int p1 = atomicAdd(&g_cursor[d1], 1);
    int p2 = atomicAdd(&g_cursor[d2], 1);
    int p3 = atomicAdd(&g_cursor[d3], 1);
    g_csr[p0] = s0;
    g_csr[p1] = s1;
    g_csr[p2] = s2;
    g_csr[p3] = s3;
}

// fused layer-2: CSR gather, ping-pong smem staging (1 syncwarp/chunk), float4
// stage reads in edge loop, float2 matmul, BN2 stats; last block finalizes BN2.
__global__ void k_l2g(const float* __restrict__ W2l, const float* __restrict__ b2l,
                      const float* __restrict__ W2r, const float* __restrict__ g2,
                      const float* __restrict__ be2) {
    __shared__ float2 sW[HH][HH];                    // sW[j][i] = (W2l[i][j], W2r[i][j])
    __shared__ float sb[HH];
    __shared__ __align__(16) float2 stage[8][3][HH]; // [warp][pingpong0/1, matmul=2][edge]

    for (int t = threadIdx.x; t < HH * HH; t += blockDim.x) {
        int i = t >> 5, j = t & 31;
        sW[j][i] = make_float2(__ldg(&W2l[i * HH + j]), __ldg(&W2r[i * HH + j]));
    }
    if (threadIdx.x < HH) sb[threadIdx.x] = __ldg(&b2l[threadIdx.x]);
    __syncthreads();

    int lane = threadIdx.x & 31;
    int wid  = threadIdx.x >> 5;
    int warp = (blockIdx.x * blockDim.x + threadIdx.x) >> 5;
    int nwarps = (gridDim.x * blockDim.x) >> 5;
    float A = g_A[lane], B = g_B[lane], C = g_C[lane];
    float reluC = fmaxf(C, 0.f);
    float s = 0.f, s2 = 0.f;

    for (int n = warp; n < NN; n += nwarps) {
        int off = g_off[n];
        int deg = (int)g_ad[n].y;
        int chunks = (deg + 31) >> 5;
        float acc = 0.f;
        for (int c = 0; c < chunks; c++) {
            int i = (c << 5) + lane;
            float2 v = make_float2(0.f, 0.f);
            if (i < deg) v = __ldg(&g_mx[__ldg(&g_csr[off + i])]);
            float2* st = stage[wid][c & 1];
            st[lane] = v;
            __syncwarp();                            // single sync: ping-pong buffers
            const float4* stp = (const float4*)st;
            float a0 = 0.f, a1 = 0.f;
#pragma unroll
            for (int jj = 0; jj < 16; jj += 2) {
                float4 u0 = stp[jj];
                float4 u1 = stp[jj + 1];
                a0 += fmaxf(fmaf(A, u0.x, fmaf(B, u0.y, C)), 0.f)
                    + fmaxf(fmaf(A, u0.z, fmaf(B, u0.w, C)), 0.f);
                a1 += fmaxf(fmaf(A, u1.x, fmaf(B, u1.y, C)), 0.f)
                    + fmaxf(fmaf(A, u1.z, fmaf(B, u1.w, C)), 0.f);
            }
            acc += a0 + a1;
        }
        acc -= (float)((chunks << 5) - deg) * reluC;   // remove zero-pad relu(C) terms
        float av = acc / fmaxf((float)deg, 1.f);
        float2 mxn = g_mx[n];
        float hr = fmaxf(fmaf(A, mxn.x, fmaf(B, mxn.y, C)), 0.f);
        float2* stm = stage[wid][2];                 // dedicated matmul buffer
        stm[lane] = make_float2(av, hr);
        __syncwarp();
        float o0 = sb[lane], o1 = 0.f, o2 = 0.f, o3 = 0.f;
#pragma unroll
        for (int j = 0; j < 32; j += 4) {
            float2 u0 = stm[j];     float2 w0 = sW[j][lane];
            float2 u1 = stm[j + 1]; float2 w1 = sW[j + 1][lane];
            float2 u2 = stm[j + 2]; float2 w2 = sW[j + 2][lane];
            float2 u3 = stm[j + 3]; float2 w3 = sW[j + 3][lane];
            o0 = fmaf(u0.x, w0.x, fmaf(u0.y, w0.y, o0));
            o1 = fmaf(u1.x, w1.x, fmaf(u1.y, w1.y, o1));
            o2 = fmaf(u2.x, w2.x, fmaf(u2.y, w2.y, o2));
            o3 = fmaf(u3.x, w3.x, fmaf(u3.y, w3.y, o3));
        }
        float outv = (o0 + o1) + (o2 + o3);
        g_h2[n * HH + lane] = outv;
        s += outv; s2 += outv * outv;
        __syncwarp();                                // protect stm before next node reuses
    }
    atomicAdd(&g_stats[lane], s);
    atomicAdd(&g_stats[HH + lane], s2);

    __syncthreads();
    if (threadIdx.x == 0) {
        __threadfence();
        if (atomicAdd(&g_cnt2, 1) == gridDim.x - 1) {
            float invN = 1.f / (float)NN;
            for (int f = 0; f < HH; f++) {
                float sum = atomicAdd(&g_stats[f], 0.f);
                float sq  = atomicAdd(&g_stats[HH + f], 0.f);
                float mean = sum * invN;
                float var = sq * invN - mean * mean;
                float sc = __ldg(&g2[f]) * rsqrtf(var + 1e-5f);
                g_scale2[f] = sc;
                g_shift2[f] = __ldg(&be2[f]) - mean * sc;
            }
        }
    }
}

__device__ __forceinline__ int lbound(const int* __restrict__ a, int n, int v) {
    int lo = 0, hi = n;
    while (lo < hi) {
        int mid = (lo + hi) >> 1;
        if (__ldg(&a[mid]) < v) lo = mid + 1; else hi = mid;
    }
    return lo;
}

// pooling: block per graph; single-pass online softmax.
__global__ void k_pool(const int* __restrict__ batch,
                       const float* __restrict__ gw, const float* __restrict__ gb,
                       const float* __restrict__ lw, const float* __restrict__ lb,
                       float* __restrict__ out) {
    int g = blockIdx.x;
    int lane = threadIdx.x & 31;
    int wid = threadIdx.x >> 5;                      // 4 warps
    int lo = lbound(batch, NN, g);
    int hi = lbound(batch, NN, g + 1);
    float lbv = __ldg(&lb[0]);
    if (lo >= hi) {
        if (threadIdx.x == 0) out[g] = 1.f / (1.f + expf(-lbv));
        return;
    }
    float w = __ldg(&gw[lane]);
    float gbv = __ldg(&gb[0]);
    float sc2 = g_scale2[lane], sh2 = g_shift2[lane];

    __shared__ float smax[4], sden[4], snum[4][HH];

    float mxs = -3.4e38f, den = 0.f, num = 0.f;
    for (int n = lo + wid; n < hi; n += 4) {
        float v = fmaxf(g_h2[n * HH + lane] * sc2 + sh2, 0.f);
        float sc = v * w;
#pragma unroll
        for (int o = 16; o; o >>= 1) sc += __shfl_xor_sync(0xffffffffu, sc, o);
        sc += gbv;
        if (sc > mxs) {
            float r = expf(mxs - sc);
            den *= r; num *= r;
            mxs = sc;
        }
        float ex = expf(sc - mxs);
        den += ex;
        num += ex * v;
    }
    if (lane == 0) smax[wid] = mxs;
    __syncthreads();
    float bmax = fmaxf(fmaxf(smax[0], smax[1]), fmaxf(smax[2], smax[3]));
    float r = expf(mxs - bmax);
    snum[wid][lane] = num * r;
    if (lane == 0) sden[wid] = den * r;
    __syncthreads();
    if (wid == 0) {
        float nm = snum[0][lane] + snum[1][lane] + snum[2][lane] + snum[3][lane];
        float dn = sden[0] + sden[1] + sden[2] + sden[3];
        float val = nm / dn * __ldg(&lw[lane]);
#pragma unroll
        for (int o = 16; o; o >>= 1) val += __shfl_xor_sync(0xffffffffu, val, o);
        if (lane == 0) out[g] = 1.f / (1.f + expf(-(val + lbv)));
    }
}

// cleanup: restore the zero-state invariant for the next graph replay
__global__ void k_clean() {
    int i = blockIdx.x * blockDim.x + threadIdx.x;
    if (i < NN) g_ad[i] = make_float2(0.f, 0.f);
    if (i < 5) g_s5[i] = 0.f;
    if (i < 2 * HH) g_stats[i] = 0.f;
    if (i == 0) { g_cnt0 = 0; g_cnt1 = 0; g_cnt2 = 0; }
}

// ---------------- launch -------------------------------------------------------

extern "C" void kernel_launch(void* const* d_in, const int* in_sizes, int n_in,
                              void* d_out, int out_size) {
    const float* x     = (const float*)d_in[0];
    const int*   ei    = (const int*)d_in[1];
    const int*   batch = (const int*)d_in[2];
    const float* W1l   = (const float*)d_in[3];
    const float* b1l   = (const float*)d_in[4];
    const float* W1r   = (const float*)d_in[5];
    const float* W2l   = (const float*)d_in[6];
    const float* b2l   = (const float*)d_in[7];
    const float* W2r   = (const float*)d_in[8];
    const float* g1    = (const float*)d_in[9];
    const float* be1   = (const float*)d_in[10];
    const float* g2    = (const float*)d_in[11];
    const float* be2   = (const float*)d_in[12];
    const float* gate_w= (const float*)d_in[13];
    const float* gate_b= (const float*)d_in[14];
    const float* lin_w = (const float*)d_in[15];
    const float* lin_b = (const float*)d_in[16];
    float* out = (float*)d_out;

    const int T = 256;
    const int blocksE  = EE / T;                 // 25000
    const int blocksE4 = EE / (T * 4);           // 6250
    const int blocksN  = (NN + T - 1) / T;       // 782
    const int blocksW  = 2048;

    k_edge1<<<blocksE, T>>>(ei, x);                               // 1
    k_scan<<<NB2, T>>>(x, W1l, b1l, W1r, g1, be1);                // 2
    k_scatter<<<blocksE4, T>>>(ei);                               // 3
    k_l2g<<<blocksW, T>>>(W2l, b2l, W2r, g2, be2);                // 4  <- profiled slot
    k_pool<<<GG, 128>>>(batch, gate_w, gate_b, lin_w, lin_b, out);// 5
    k_clean<<<blocksN, T>>>();                                    // 6
}

// round 17
// speedup vs baseline: 1.0918x; 1.0816x over previous
#include <cuda_runtime.h>

#define NN 200000
#define EE 6400000
#define GG 2048
#define HH 32
#define NB2 196   // ceil(NN/1024)

// ---------------- scratch -----------------------------------------------------
__device__ __align__(16) float2 g_ad[NN];        // (sum_x, deg); zeroed by pool-prologue/static init
__device__ __align__(16) float2 g_mx[NN];        // (m, x)
__device__ int   g_off[NN];
__device__ int   g_cursor[NN];
__device__ int   g_bsum[NB2];
__device__ int   g_csr[EE];
__device__ __align__(16) float g_h2[NN * HH];
__device__ float g_s5[5];
__device__ float g_stats[2 * HH];
__device__ __align__(16) float g_A[HH], g_B[HH], g_C[HH];
__device__ float g_scale2[HH], g_shift2[HH];
__device__ int   g_cnt0, g_cnt1, g_cnt2;

// ---------------- kernels -----------------------------------------------------

__global__ void k_edge1(const int* __restrict__ ei, const float* __restrict__ x) {
    int e = blockIdx.x * blockDim.x + threadIdx.x;   // covers EE exactly
    int s = __ldg(&ei[e]);
    int d = __ldg(&ei[EE + e]);
    float xv = __ldg(&x[s]);
    float* p = (float*)&g_ad[d];
    asm volatile("red.global.add.v2.f32 [%0], {%1,%2};"
                 :: "l"(p), "f"(xv), "f"(1.0f) : "memory");
}

// fused scan: per-block tile scan + device-wide spin barrier + base recompute,
// then offsets/cursor/(m,x)/moments; last block computes A,B,C.
__global__ void k_scan(const float* __restrict__ x, const float* __restrict__ W1l,
                       const float* __restrict__ b1l, const float* __restrict__ W1r,
                       const float* __restrict__ g1, const float* __restrict__ be1) {
    __shared__ int sm[256];
    __shared__ int sw[8];
    int b = blockIdx.x, t = threadIdx.x;
    int lane = t & 31, wid = t >> 5;
    int n0 = b * 1024 + t * 4;

    int s = 0;
#pragma unroll
    for (int k = 0; k < 4; k++) { int n = n0 + k; if (n < NN) s += (int)g_ad[n].y; }
    sm[t] = s; __syncthreads();
    for (int o = 1; o < 256; o <<= 1) {
        int u = (t >= o) ? sm[t - o] : 0;
        __syncthreads(); sm[t] += u; __syncthreads();
    }
    int ex = sm[t] - s;
    if (t == 255) g_bsum[b] = sm[255];

    __syncthreads();
    if (t == 0) {
        __threadfence();
        atomicAdd(&g_cnt0, 1);
        while (atomicAdd(&g_cnt0, 0) < (int)gridDim.x) { }
    }
    __syncthreads();
    __threadfence();

    int v = (t < b) ? g_bsum[t] : 0;
    int r = v;
#pragma unroll
    for (int o = 16; o; o >>= 1) r += __shfl_xor_sync(0xffffffffu, r, o);
    if (lane == 0) sw[wid] = r;
    __syncthreads();
    int base = sw[0] + sw[1] + sw[2] + sw[3] + sw[4] + sw[5] + sw[6] + sw[7] + ex;

    float m0 = 0.f, m1 = 0.f, m2 = 0.f, m3 = 0.f, m4 = 0.f;
#pragma unroll
    for (int k = 0; k < 4; k++) {
        int n = n0 + k;
        if (n < NN) {
            float2 ad = g_ad[n];
            g_off[n] = base; g_cursor[n] = base;
            base += (int)ad.y;
            float m = ad.x / fmaxf(ad.y, 1.f);
            float xv = __ldg(&x[n]);
            g_mx[n] = make_float2(m, xv);
            m0 += m; m1 += xv; m2 += m * m; m3 += xv * xv; m4 += m * xv;
        }
    }
#pragma unroll
    for (int o = 16; o; o >>= 1) {
        m0 += __shfl_xor_sync(0xffffffffu, m0, o);
        m1 += __shfl_xor_sync(0xffffffffu, m1, o);
        m2 += __shfl_xor_sync(0xffffffffu, m2, o);
        m3 += __shfl_xor_sync(0xffffffffu, m3, o);
        m4 += __shfl_xor_sync(0xffffffffu, m4, o);
    }
    if (lane == 0) {
        atomicAdd(&g_s5[0], m0); atomicAdd(&g_s5[1], m1);
        atomicAdd(&g_s5[2], m2); atomicAdd(&g_s5[3], m3);
        atomicAdd(&g_s5[4], m4);
    }
    __syncthreads();
    if (t == 0) {
        __threadfence();
        if (atomicAdd(&g_cnt1, 1) == gridDim.x - 1) {
            float s0 = atomicAdd(&g_s5[0], 0.f), s1 = atomicAdd(&g_s5[1], 0.f);
            float s2 = atomicAdd(&g_s5[2], 0.f), s3 = atomicAdd(&g_s5[3], 0.f);
            float s4 = atomicAdd(&g_s5[4], 0.f);
            float invN = 1.f / (float)NN;
            float Mm = s0 * invN, Mx = s1 * invN;
            float Vm = s2 * invN - Mm * Mm;
            float Vx = s3 * invN - Mx * Mx;
            float Cmx = s4 * invN - Mm * Mx;
            for (int f = 0; f < HH; f++) {
                float wlv = __ldg(&W1l[f]), wrv = __ldg(&W1r[f]), bv = __ldg(&b1l[f]);
                float mean = wlv * Mm + wrv * Mx + bv;
                float var = wlv * wlv * Vm + wrv * wrv * Vx + 2.f * wlv * wrv * Cmx;
                float sc = __ldg(&g1[f]) * rsqrtf(var + 1e-5f);
                g_A[f] = sc * wlv;
                g_B[f] = sc * wrv;
                g_C[f] = sc * bv + __ldg(&be1[f]) - sc * mean;
            }
        }
    }
}

// index scatter with 4-way ILP
__global__ void k_scatter(const int* __restrict__ ei) {
    const int total = (EE / 4);
    int t = blockIdx.x * blockDim.x + threadIdx.x;   // grid covers EE/4 exactly
    int e0 = t, e1 = t + total, e2 = t + 2 * total, e3 = t + 3 * total;
    int s0 = __ldg(&ei[e0]), s1 = __ldg(&ei[e1]);
    int s2 = __ldg(&ei[e2]), s3 = __ldg(&ei[e3]);
    int d0 = __ldg(&ei[EE + e0]), d1 = __ldg(&ei[EE + e1]);
    int d2 = __ldg(&ei[EE + e2]), d3 = __ldg(&ei[EE + e3]);
    int p0 = atomicAdd(&g_cursor[d0], 1);
    int p1 = atomicAdd(&g_cursor[d1], 1);
    int p2 = atomicAdd(&g_cursor[d2], 1);
    int p3 = atomicAdd(&g_cursor[d3], 1);
    g_csr[p0] = s0;
    g_csr[p1] = s1;
    g_csr[p2] = s2;
    g_csr[p3] = s3;
}

// fused layer-2: CSR gather + smem-staged float2 broadcasts, packed-weight matmul,
// BN2 stats; last block finalizes BN2 scale/shift. (R11 shape; grid = 1 wave.)
__global__ void k_l2g(const float* __restrict__ W2l, const float* __restrict__ b2l,
                      const float* __restrict__ W2r, const float* __restrict__ g2,
                      const float* __restrict__ be2) {
    __shared__ float2 sW[HH][HH];       // sW[j][i] = (W2l[i][j], W2r[i][j])
    __shared__ float sb[HH];
    __shared__ float2 stage[8][HH];     // per-warp staging buffer

    for (int t = threadIdx.x; t < HH * HH; t += blockDim.x) {
        int i = t >> 5, j = t & 31;
        sW[j][i] = make_float2(__ldg(&W2l[i * HH + j]), __ldg(&W2r[i * HH + j]));
    }
    if (threadIdx.x < HH) sb[threadIdx.x] = __ldg(&b2l[threadIdx.x]);
    __syncthreads();

    int lane = threadIdx.x & 31;
    int wid  = threadIdx.x >> 5;
    int warp = (blockIdx.x * blockDim.x + threadIdx.x) >> 5;
    int nwarps = (gridDim.x * blockDim.x) >> 5;
    float A = g_A[lane], B = g_B[lane], C = g_C[lane];
    float s = 0.f, s2 = 0.f;
    float2* st = stage[wid];

    for (int n = warp; n < NN; n += nwarps) {
        int off = g_off[n];
        int deg = (int)g_ad[n].y;
        int full = deg & ~31;
        float acc = 0.f;
        for (int base = 0; base < full; base += 32) {
            float2 mxe = __ldg(&g_mx[__ldg(&g_csr[off + base + lane])]);
            __syncwarp();
            st[lane] = mxe;
            __syncwarp();
            float a0 = 0.f, a1 = 0.f, a2 = 0.f, a3 = 0.f;
#pragma unroll
            for (int j = 0; j < 32; j += 4) {
                float2 u0 = st[j];
                float2 u1 = st[j + 1];
                float2 u2 = st[j + 2];
                float2 u3 = st[j + 3];
                a0 += fmaxf(fmaf(A, u0.x, fmaf(B, u0.y, C)), 0.f);
                a1 += fmaxf(fmaf(A, u1.x, fmaf(B, u1.y, C)), 0.f);
                a2 += fmaxf(fmaf(A, u2.x, fmaf(B, u2.y, C)), 0.f);
                a3 += fmaxf(fmaf(A, u3.x, fmaf(B, u3.y, C)), 0.f);
            }
            acc += (a0 + a1) + (a2 + a3);
        }
        int rem = deg - full;
        if (rem) {
            float2 mxe = make_float2(0.f, 0.f);
            if (lane < rem) mxe = __ldg(&g_mx[__ldg(&g_csr[off + full + lane])]);
            __syncwarp();
            st[lane] = mxe;
            __syncwarp();
            for (int j = 0; j < rem; j++) {
                float2 u = st[j];
                acc += fmaxf(fmaf(A, u.x, fmaf(B, u.y, C)), 0.f);
            }
        }
        float av = acc / fmaxf((float)deg, 1.f);
        float2 mxn = g_mx[n];
        float hr = fmaxf(fmaf(A, mxn.x, fmaf(B, mxn.y, C)), 0.f);
        __syncwarp();
        st[lane] = make_float2(av, hr);
        __syncwarp();
        float o0 = sb[lane], o1 = 0.f, o2 = 0.f, o3 = 0.f;
#pragma unroll
        for (int j = 0; j < 32; j += 4) {
            float2 u0 = st[j];     float2 w0 = sW[j][lane];
            float2 u1 = st[j + 1]; float2 w1 = sW[j + 1][lane];
            float2 u2 = st[j + 2]; float2 w2 = sW[j + 2][lane];
            float2 u3 = st[j + 3]; float2 w3 = sW[j + 3][lane];
            o0 = fmaf(u0.x, w0.x, fmaf(u0.y, w0.y, o0));
            o1 = fmaf(u1.x, w1.x, fmaf(u1.y, w1.y, o1));
            o2 = fmaf(u2.x, w2.x, fmaf(u2.y, w2.y, o2));
            o3 = fmaf(u3.x, w3.x, fmaf(u3.y, w3.y, o3));
        }
        float outv = (o0 + o1) + (o2 + o3);
        g_h2[n * HH + lane] = outv;
        s += outv; s2 += outv * outv;
    }
    atomicAdd(&g_stats[lane], s);
    atomicAdd(&g_stats[HH + lane], s2);

    __syncthreads();
    if (threadIdx.x == 0) {
        __threadfence();
        if (atomicAdd(&g_cnt2, 1) == gridDim.x - 1) {
            float invN = 1.f / (float)NN;
            for (int f = 0; f < HH; f++) {
                float sum = atomicAdd(&g_stats[f], 0.f);
                float sq  = atomicAdd(&g_stats[HH + f], 0.f);
                float mean = sum * invN;
                float var = sq * invN - mean * mean;
                float sc = __ldg(&g2[f]) * rsqrtf(var + 1e-5f);
                g_scale2[f] = sc;
                g_shift2[f] = __ldg(&be2[f]) - mean * sc;
            }
        }
    }
}

__device__ __forceinline__ int lbound(const int* __restrict__ a, int n, int v) {
    int lo = 0, hi = n;
    while (lo < hi) {
        int mid = (lo + hi) >> 1;
        if (__ldg(&a[mid]) < v) lo = mid + 1; else hi = mid;
    }
    return lo;
}

// pooling: block per graph; single-pass online softmax. Prologue restores the
// zero-state invariant for the next graph replay (disjoint from pool's reads).
__global__ void k_pool(const int* __restrict__ batch,
                       const float* __restrict__ gw, const float* __restrict__ gb,
                       const float* __restrict__ lw, const float* __restrict__ lb,
                       float* __restrict__ out) {
    // --- cleanup prologue (grid 2048 x 128 covers NN) ---
    int ci = blockIdx.x * blockDim.x + threadIdx.x;
    if (ci < NN) g_ad[ci] = make_float2(0.f, 0.f);
    if (ci < 5) g_s5[ci] = 0.f;
    if (ci < 2 * HH) g_stats[ci] = 0.f;
    if (ci == 0) { g_cnt0 = 0; g_cnt1 = 0; g_cnt2 = 0; }

    int g = blockIdx.x;
    int lane = threadIdx.x & 31;
    int wid = threadIdx.x >> 5;                      // 4 warps
    int lo = lbound(batch, NN, g);
    int hi = lbound(batch, NN, g + 1);
    float lbv = __ldg(&lb[0]);
    if (lo >= hi) {
        if (threadIdx.x == 0) out[g] = 1.f / (1.f + expf(-lbv));
        return;
    }
    float w = __ldg(&gw[lane]);
    float gbv = __ldg(&gb[0]);
    float sc2 = g_scale2[lane], sh2 = g_shift2[lane];

    __shared__ float smax[4], sden[4], snum[4][HH];

    float mxs = -3.4e38f, den = 0.f, num = 0.f;
    for (int n = lo + wid; n < hi; n += 4) {
        float v = fmaxf(g_h2[n * HH + lane] * sc2 + sh2, 0.f);
        float sc = v * w;
#pragma unroll
        for (int o = 16; o; o >>= 1) sc += __shfl_xor_sync(0xffffffffu, sc, o);
        sc += gbv;
        if (sc > mxs) {
            float r = expf(mxs - sc);
            den *= r; num *= r;
            mxs = sc;
        }
        float ex = expf(sc - mxs);
        den += ex;
        num += ex * v;
    }
    if (lane == 0) smax[wid] = mxs;
    __syncthreads();
    float bmax = fmaxf(fmaxf(smax[0], smax[1]), fmaxf(smax[2], smax[3]));
    float r = expf(mxs - bmax);
    snum[wid][lane] = num * r;
    if (lane == 0) sden[wid] = den * r;
    __syncthreads();
    if (wid == 0) {
        float nm = snum[0][lane] + snum[1][lane] + snum[2][lane] + snum[3][lane];
        float dn = sden[0] + sden[1] + sden[2] + sden[3];
        float val = nm / dn * __ldg(&lw[lane]);
#pragma unroll
        for (int o = 16; o; o >>= 1) val += __shfl_xor_sync(0xffffffffu, val, o);
        if (lane == 0) out[g] = 1.f / (1.f + expf(-(val + lbv)));
    }
}

// ---------------- launch -------------------------------------------------------

extern "C" void kernel_launch(void* const* d_in, const int* in_sizes, int n_in,
                              void* d_out, int out_size) {
    const float* x     = (const float*)d_in[0];
    const int*   ei    = (const int*)d_in[1];
    const int*   batch = (const int*)d_in[2];
    const float* W1l   = (const float*)d_in[3];
    const float* b1l   = (const float*)d_in[4];
    const float* W1r   = (const float*)d_in[5];
    const float* W2l   = (const float*)d_in[6];
    const float* b2l   = (const float*)d_in[7];
    const float* W2r   = (const float*)d_in[8];
    const float* g1    = (const float*)d_in[9];
    const float* be1   = (const float*)d_in[10];
    const float* g2    = (const float*)d_in[11];
    const float* be2   = (const float*)d_in[12];
    const float* gate_w= (const float*)d_in[13];
    const float* gate_b= (const float*)d_in[14];
    const float* lin_w = (const float*)d_in[15];
    const float* lin_b = (const float*)d_in[16];
    float* out = (float*)d_out;

    const int T = 256;
    const int blocksE  = EE / T;                 // 25000
    const int blocksE4 = EE / (T * 4);           // 6250
    const int blocksW  = 148 * 8;                // 1184: single wave at 32 regs

    k_edge1<<<blocksE, T>>>(ei, x);                               // 1
    k_scan<<<NB2, T>>>(x, W1l, b1l, W1r, g1, be1);                // 2
    k_scatter<<<blocksE4, T>>>(ei);                               // 3
    k_l2g<<<blocksW, T>>>(W2l, b2l, W2r, g2, be2);                // 4  <- profiled slot
    k_pool<<<GG, 128>>>(batch, gate_w, gate_b, lin_w, lin_b, out);// 5
}